// round 3
// baseline (speedup 1.0000x reference)
#include <cuda_runtime.h>
#include <cstdint>

#define BS   64
#define NQ   3000
#define NC   256
#define FH   100
#define FW   100
#define TOPK 1500

// Scratch for per-(b,q) scores (no cudaMalloc allowed).
__device__ float g_scores[BS * NQ];

// ---------------------------------------------------------------------------
// Kernel 1: scores[b,q] = max over NC=256 classes. One warp per row.
// Each lane: 2x float4 loads (512B/warp/load, fully coalesced), warp shfl max.
// ---------------------------------------------------------------------------
__global__ __launch_bounds__(256) void scores_kernel(const float* __restrict__ cls) {
    int warp_global = (blockIdx.x * blockDim.x + threadIdx.x) >> 5;
    int lane = threadIdx.x & 31;
    if (warp_global >= BS * NQ) return;

    const float4* row = reinterpret_cast<const float4*>(cls + (size_t)warp_global * NC);
    float4 a = row[lane];
    float4 b = row[lane + 32];
    float m = fmaxf(fmaxf(fmaxf(a.x, a.y), fmaxf(a.z, a.w)),
                    fmaxf(fmaxf(b.x, b.y), fmaxf(b.z, b.w)));
#pragma unroll
    for (int o = 16; o; o >>= 1)
        m = fmaxf(m, __shfl_xor_sync(0xFFFFFFFFu, m, o));
    if (lane == 0) g_scores[warp_global] = m;
}

// Monotone float -> uint key (total order matches float compare for finite vals)
__device__ __forceinline__ unsigned f2key(float f) {
    unsigned u = __float_as_uint(f);
    return u ^ ((u >> 31) ? 0xFFFFFFFFu : 0x80000000u);
}

// ---------------------------------------------------------------------------
// Kernel 2: per-batch fused top-k selection + rectangle-union mask paint.
// One block per batch, 1024 threads.
// ---------------------------------------------------------------------------
__global__ __launch_bounds__(1024) void mask_kernel(const float* __restrict__ coord,
                                                    const int*   __restrict__ vfs,
                                                    float*       __restrict__ out) {
    const int b    = blockIdx.x;
    const int tid  = threadIdx.x;
    const int lane = tid & 31;
    const int wid  = tid >> 5;

    __shared__ unsigned s_red[33];        // block reductions
    __shared__ unsigned s_woff[32];       // scan warp offsets
    __shared__ unsigned s_lyry[TOPK];     // packed (ly | ry<<16)
    __shared__ unsigned s_m[4][TOPK];     // column bitmasks (4 x u32 = 128 bits)
    __shared__ unsigned s_bitmap[FH][4];  // row coverage bitmaps
    __shared__ int      s_nrect;

    // ---- init shared state ----
    if (tid == 0) s_nrect = 0;
    for (int i = tid; i < FH * 4; i += 1024)
        (&s_bitmap[0][0])[i] = 0u;

    // ---- load keys: 3 contiguous queries per thread ----
    unsigned k[3];
#pragma unroll
    for (int j = 0; j < 3; j++) {
        int q = tid * 3 + j;
        k[j] = (q < NQ) ? f2key(g_scores[b * NQ + q]) : 0u;
    }

    // block-wide count of keys >= x (x >= 1 so invalid keys(=0) never count)
    auto block_count_ge = [&](unsigned x) -> unsigned {
        unsigned c = 0;
#pragma unroll
        for (int j = 0; j < 3; j++) c += (k[j] >= x);
#pragma unroll
        for (int o = 16; o; o >>= 1) c += __shfl_down_sync(0xFFFFFFFFu, c, o);
        __syncthreads();                 // protect s_red reuse across calls
        if (lane == 0) s_red[wid] = c;
        __syncthreads();
        if (tid < 32) {
            unsigned v = s_red[lane];
#pragma unroll
            for (int o = 16; o; o >>= 1) v += __shfl_down_sync(0xFFFFFFFFu, v, o);
            if (lane == 0) s_red[32] = v;
        }
        __syncthreads();
        return s_red[32];
    };

    // ---- binary search for T = max{x : count_ge(x) >= TOPK} ----
    unsigned lo = 0u, hi = 0xFFFFFFFFu;
    while (lo < hi) {
        unsigned mid = lo + ((hi - lo) >> 1) + 1u;
        unsigned c = block_count_ge(mid);
        if (c >= TOPK) lo = mid; else hi = mid - 1u;
    }
    const unsigned T = lo;
    const unsigned cnt_gt  = (T == 0xFFFFFFFFu) ? 0u : block_count_ge(T + 1u);
    const unsigned need_eq = TOPK - cnt_gt;

    // ---- exclusive scan of (#keys == T) per thread, for index-order ties ----
    unsigned e = 0;
#pragma unroll
    for (int j = 0; j < 3; j++) e += (k[j] == T);
    unsigned inc = e;
#pragma unroll
    for (int o = 1; o < 32; o <<= 1) {
        unsigned v = __shfl_up_sync(0xFFFFFFFFu, inc, o);
        if (lane >= o) inc += v;
    }
    if (lane == 31) s_woff[wid] = inc;
    __syncthreads();
    if (tid < 32) {
        unsigned v = s_woff[lane];
        unsigned i2 = v;
#pragma unroll
        for (int o = 1; o < 32; o <<= 1) {
            unsigned u = __shfl_up_sync(0xFFFFFFFFu, i2, o);
            if (lane >= o) i2 += u;
        }
        s_woff[lane] = i2 - v;           // exclusive warp offsets
    }
    __syncthreads();
    const unsigned my_off = s_woff[wid] + (inc - e);

    // ---- build rects for selected queries ----
    const float fvh = (float)vfs[b * 2 + 0];
    const float fvw = (float)vfs[b * 2 + 1];
    unsigned cum = 0;
#pragma unroll
    for (int j = 0; j < 3; j++) {
        int q = tid * 3 + j;
        bool sel = false;
        if (q < NQ) {
            if (k[j] > T) sel = true;
            else if (k[j] == T) { sel = (my_off + cum < need_eq); cum++; }
        }
        if (sel) {
            float4 c4 = *reinterpret_cast<const float4*>(coord + ((size_t)b * NQ + q) * 4);
            // Non-contracted IEEE ops to match XLA bit-for-bit at floor boundaries
            float hw = __fmul_rn(0.5f, c4.z);
            float hh = __fmul_rn(0.5f, c4.w);
            float x0 = __fsub_rn(c4.x, hw);
            float y0 = __fsub_rn(c4.y, hh);
            float x1 = __fadd_rn(c4.x, hw);
            float y1 = __fadd_rn(c4.y, hh);
            int lx = (int)floorf(__fmul_rn(x0, fvh));
            int ly = (int)floorf(__fmul_rn(y0, fvw));
            int rx = (int)floorf(__fmul_rn(x1, fvh));
            int ry = (int)floorf(__fmul_rn(y1, fvw));
            int lc  = max(lx, 0), rc  = min(rx, FW);
            int lyc = max(ly, 0), ryc = min(ry, FH);
            if (ryc < lyc) ryc = lyc;    // empty row range
            int slot = atomicAdd(&s_nrect, 1);
            s_lyry[slot] = (unsigned)lyc | ((unsigned)ryc << 16);
#pragma unroll
            for (int w = 0; w < 4; w++) {
                int l = min(max(lc - 32 * w, 0), 32);
                int h = min(max(rc - 32 * w, 0), 32);
                unsigned m = 0;
                if (h > l) {
                    unsigned mh = (h == 32) ? 0xFFFFFFFFu : ((1u << h) - 1u);
                    m = mh & ~((1u << l) - 1u);   // l < 32 guaranteed here
                }
                s_m[w][slot] = m;
            }
        }
    }
    __syncthreads();

    // ---- paint: thread = (row = tid&127, slice = tid>>7); slices stride rects
    // slice is warp-uniform -> rect reads are smem broadcasts.
    const int nrect = s_nrect;
    {
        int row   = tid & 127;
        int slice = tid >> 7;
        if (row < FH) {
            unsigned r0 = 0, r1 = 0, r2 = 0, r3 = 0;
            for (int i = slice; i < nrect; i += 8) {
                unsigned lr = s_lyry[i];
                int ly = (int)(lr & 0xFFFFu), ry = (int)(lr >> 16);
                if (row >= ly && row < ry) {
                    r0 |= s_m[0][i]; r1 |= s_m[1][i];
                    r2 |= s_m[2][i]; r3 |= s_m[3][i];
                }
            }
            if (r0) atomicOr(&s_bitmap[row][0], r0);
            if (r1) atomicOr(&s_bitmap[row][1], r1);
            if (r2) atomicOr(&s_bitmap[row][2], r2);
            if (r3) atomicOr(&s_bitmap[row][3], r3);
        }
    }
    __syncthreads();

    // ---- write output: masked (-1e20) unless covered && !padding ----
    const int vh = vfs[b * 2 + 0];
    const int vw = vfs[b * 2 + 1];
    float* obase = out + (size_t)b * FH * FW;
    for (int idx = tid; idx < FH * FW; idx += 1024) {
        int h = idx / FW;
        int w = idx - h * FW;
        bool cov = (s_bitmap[h][w >> 5] >> (w & 31)) & 1u;
        bool pad = (h >= vh) || (w >= vw);
        obase[idx] = (cov && !pad) ? 0.0f : -1e20f;
    }
}

// ---------------------------------------------------------------------------
extern "C" void kernel_launch(void* const* d_in, const int* in_sizes, int n_in,
                              void* d_out, int out_size) {
    const float* coord = (const float*)d_in[0];  // (BS, NQ, 4) f32
    const float* cls   = (const float*)d_in[1];  // (BS, NQ, NC) f32
    const int*   vfs   = (const int*)d_in[2];    // (BS, 2) i32
    float* out = (float*)d_out;                  // (BS, FH*FW) f32

    int nwarps = BS * NQ;                        // one warp per (b,q) row
    int threads = 256;
    int blocks = (nwarps * 32 + threads - 1) / threads;  // 24000
    scores_kernel<<<blocks, threads>>>(cls);
    mask_kernel<<<BS, 1024>>>(coord, vfs, out);
}

// round 4
// speedup vs baseline: 1.2208x; 1.2208x over previous
#include <cuda_runtime.h>
#include <cstdint>

#define BS   64
#define NQ   3000
#define NC   256
#define FH   100
#define FW   100
#define TOPK 1500

// Scratch for per-(b,q) scores (no cudaMalloc allowed).
__device__ float g_scores[BS * NQ];

// ---------------------------------------------------------------------------
// Kernel 1: scores[b,q] = max over NC=256 classes. One warp per 4 rows.
// 8 independent LDG.128 per thread (MLP_p1=8) to hide DRAM latency.
// ---------------------------------------------------------------------------
__global__ __launch_bounds__(256) void scores_kernel(const float* __restrict__ cls) {
    int warp = (blockIdx.x * blockDim.x + threadIdx.x) >> 5;
    int lane = threadIdx.x & 31;
    int row0 = warp * 4;
    if (row0 >= BS * NQ) return;

    const float4* r0 = reinterpret_cast<const float4*>(cls + (size_t)(row0 + 0) * NC);
    const float4* r1 = reinterpret_cast<const float4*>(cls + (size_t)(row0 + 1) * NC);
    const float4* r2 = reinterpret_cast<const float4*>(cls + (size_t)(row0 + 2) * NC);
    const float4* r3 = reinterpret_cast<const float4*>(cls + (size_t)(row0 + 3) * NC);

    float4 a0 = __ldcs(&r0[lane]);
    float4 b0 = __ldcs(&r0[lane + 32]);
    float4 a1 = __ldcs(&r1[lane]);
    float4 b1 = __ldcs(&r1[lane + 32]);
    float4 a2 = __ldcs(&r2[lane]);
    float4 b2 = __ldcs(&r2[lane + 32]);
    float4 a3 = __ldcs(&r3[lane]);
    float4 b3 = __ldcs(&r3[lane + 32]);

    float m0 = fmaxf(fmaxf(fmaxf(a0.x, a0.y), fmaxf(a0.z, a0.w)),
                     fmaxf(fmaxf(b0.x, b0.y), fmaxf(b0.z, b0.w)));
    float m1 = fmaxf(fmaxf(fmaxf(a1.x, a1.y), fmaxf(a1.z, a1.w)),
                     fmaxf(fmaxf(b1.x, b1.y), fmaxf(b1.z, b1.w)));
    float m2 = fmaxf(fmaxf(fmaxf(a2.x, a2.y), fmaxf(a2.z, a2.w)),
                     fmaxf(fmaxf(b2.x, b2.y), fmaxf(b2.z, b2.w)));
    float m3 = fmaxf(fmaxf(fmaxf(a3.x, a3.y), fmaxf(a3.z, a3.w)),
                     fmaxf(fmaxf(b3.x, b3.y), fmaxf(b3.z, b3.w)));
#pragma unroll
    for (int o = 16; o; o >>= 1) {
        m0 = fmaxf(m0, __shfl_xor_sync(0xFFFFFFFFu, m0, o));
        m1 = fmaxf(m1, __shfl_xor_sync(0xFFFFFFFFu, m1, o));
        m2 = fmaxf(m2, __shfl_xor_sync(0xFFFFFFFFu, m2, o));
        m3 = fmaxf(m3, __shfl_xor_sync(0xFFFFFFFFu, m3, o));
    }
    if (lane == 0)
        *reinterpret_cast<float4*>(&g_scores[row0]) = make_float4(m0, m1, m2, m3);
}

// Monotone float -> uint key (total order matches float compare for finite vals)
__device__ __forceinline__ unsigned f2key(float f) {
    unsigned u = __float_as_uint(f);
    return u ^ ((u >> 31) ? 0xFFFFFFFFu : 0x80000000u);
}

// ---------------------------------------------------------------------------
// Kernel 2: per-batch radix top-k threshold + rectangle-union mask paint.
// One block per batch, 1024 threads.
// ---------------------------------------------------------------------------
__global__ __launch_bounds__(1024) void mask_kernel(const float* __restrict__ coord,
                                                    const int*   __restrict__ vfs,
                                                    float*       __restrict__ out) {
    const int b    = blockIdx.x;
    const int tid  = threadIdx.x;
    const int lane = tid & 31;
    const int wid  = tid >> 5;

    __shared__ unsigned s_hist[256];      // radix histogram
    __shared__ unsigned s_sel[2];         // {selected byte, remaining need}
    __shared__ unsigned s_woff[32];       // scan warp offsets
    __shared__ unsigned s_lyry[TOPK];     // packed (ly | ry<<16)
    __shared__ unsigned s_m[4][TOPK];     // column bitmasks (4 x u32 = 128 bits)
    __shared__ unsigned s_bitmap[FH][4];  // row coverage bitmaps

    // ---- init shared state ----
    for (int i = tid; i < FH * 4; i += 1024)
        (&s_bitmap[0][0])[i] = 0u;

    // ---- load keys: 3 contiguous queries per thread (index order = scan order)
    unsigned k[3];
#pragma unroll
    for (int j = 0; j < 3; j++) {
        int q = tid * 3 + j;
        k[j] = (q < NQ) ? f2key(g_scores[b * NQ + q]) : 0u;
    }

    // ---- 8-bit radix select: find T = max{x : count_ge(x) >= TOPK} ----
    unsigned prefix = 0;
    unsigned need = TOPK;
#pragma unroll
    for (int pass = 0; pass < 4; pass++) {
        const int shift = 24 - 8 * pass;
        if (tid < 256) s_hist[tid] = 0u;
        __syncthreads();
#pragma unroll
        for (int j = 0; j < 3; j++) {
            unsigned kk = k[j];
            bool active = (pass == 0) || ((kk >> (shift + 8)) == prefix);
            if (active) atomicAdd(&s_hist[(kk >> shift) & 255u], 1u);
        }
        __syncthreads();
        if (tid < 32) {
            unsigned loc[8]; unsigned s = 0;
#pragma unroll
            for (int i = 0; i < 8; i++) { loc[i] = s_hist[lane * 8 + i]; s += loc[i]; }
            // v = sum over lanes >= lane (i.e. bins above mine + mine)
            unsigned v = s;
#pragma unroll
            for (int o = 1; o < 32; o <<= 1) {
                unsigned u = __shfl_down_sync(0xFFFFFFFFu, v, o);
                if (lane + o < 32) v += u;
            }
            unsigned excl = v - s;   // count in strictly higher 8-bin groups
            if (excl < need && excl + s >= need) {
                unsigned cum = excl;
#pragma unroll
                for (int i = 7; i >= 0; i--) {
                    unsigned c2 = cum + loc[i];
                    if (cum < need && c2 >= need) {
                        s_sel[0] = (unsigned)(lane * 8 + i);
                        s_sel[1] = need - cum;    // ties still required
                    }
                    cum = c2;
                }
            }
        }
        __syncthreads();
        prefix = (prefix << 8) | s_sel[0];
        need   = s_sel[1];
        __syncthreads();
    }
    const unsigned T = prefix;
    const unsigned need_eq = need;

    // ---- block exclusive scan helper (inline twice) ----
    // (1) tie scan: rank among k==T in index order
    unsigned e = 0;
#pragma unroll
    for (int j = 0; j < 3; j++) e += (k[j] == T);
    unsigned my_off;
    {
        unsigned inc = e;
#pragma unroll
        for (int o = 1; o < 32; o <<= 1) {
            unsigned u = __shfl_up_sync(0xFFFFFFFFu, inc, o);
            if (lane >= o) inc += u;
        }
        if (lane == 31) s_woff[wid] = inc;
        __syncthreads();
        if (tid < 32) {
            unsigned v = s_woff[lane], i2 = v;
#pragma unroll
            for (int o = 1; o < 32; o <<= 1) {
                unsigned u = __shfl_up_sync(0xFFFFFFFFu, i2, o);
                if (lane >= o) i2 += u;
            }
            s_woff[lane] = i2 - v;
        }
        __syncthreads();
        my_off = s_woff[wid] + (inc - e);
    }

    // ---- selection flags + slot scan (no atomics) ----
    bool selj[3];
    unsigned selc = 0;
    {
        unsigned cum = 0;
#pragma unroll
        for (int j = 0; j < 3; j++) {
            int q = tid * 3 + j;
            bool s = false;
            if (q < NQ) {
                if (k[j] > T) s = true;
                else if (k[j] == T) { s = (my_off + cum < need_eq); cum++; }
            }
            selj[j] = s;
            selc += s;
        }
    }
    unsigned slot;
    {
        unsigned inc = selc;
#pragma unroll
        for (int o = 1; o < 32; o <<= 1) {
            unsigned u = __shfl_up_sync(0xFFFFFFFFu, inc, o);
            if (lane >= o) inc += u;
        }
        __syncthreads();                 // protect s_woff reuse
        if (lane == 31) s_woff[wid] = inc;
        __syncthreads();
        if (tid < 32) {
            unsigned v = s_woff[lane], i2 = v;
#pragma unroll
            for (int o = 1; o < 32; o <<= 1) {
                unsigned u = __shfl_up_sync(0xFFFFFFFFu, i2, o);
                if (lane >= o) i2 += u;
            }
            s_woff[lane] = i2 - v;
        }
        __syncthreads();
        slot = s_woff[wid] + (inc - selc);
    }

    // ---- build rects for selected queries ----
    const float fvh = (float)vfs[b * 2 + 0];
    const float fvw = (float)vfs[b * 2 + 1];
#pragma unroll
    for (int j = 0; j < 3; j++) {
        if (selj[j]) {
            int q = tid * 3 + j;
            float4 c4 = *reinterpret_cast<const float4*>(coord + ((size_t)b * NQ + q) * 4);
            // Non-contracted IEEE ops to match XLA bit-for-bit at floor boundaries
            float hw = __fmul_rn(0.5f, c4.z);
            float hh = __fmul_rn(0.5f, c4.w);
            float x0 = __fsub_rn(c4.x, hw);
            float y0 = __fsub_rn(c4.y, hh);
            float x1 = __fadd_rn(c4.x, hw);
            float y1 = __fadd_rn(c4.y, hh);
            int lx = (int)floorf(__fmul_rn(x0, fvh));
            int ly = (int)floorf(__fmul_rn(y0, fvw));
            int rx = (int)floorf(__fmul_rn(x1, fvh));
            int ry = (int)floorf(__fmul_rn(y1, fvw));
            int lc  = max(lx, 0), rc  = min(rx, FW);
            int lyc = max(ly, 0), ryc = min(ry, FH);
            if (ryc < lyc) ryc = lyc;    // empty row range
            s_lyry[slot] = (unsigned)lyc | ((unsigned)ryc << 16);
#pragma unroll
            for (int w = 0; w < 4; w++) {
                int l = min(max(lc - 32 * w, 0), 32);
                int h = min(max(rc - 32 * w, 0), 32);
                unsigned m = 0;
                if (h > l) {
                    unsigned mh = (h == 32) ? 0xFFFFFFFFu : ((1u << h) - 1u);
                    m = mh & ~((1u << l) - 1u);   // l < 32 guaranteed here
                }
                s_m[w][slot] = m;
            }
            slot++;
        }
    }
    __syncthreads();

    // ---- paint: thread = (row = tid&127, slice = tid>>7); slices stride rects
    // slice is warp-uniform -> rect reads are smem broadcasts.
    {
        int row   = tid & 127;
        int slice = tid >> 7;
        if (row < FH) {
            unsigned r0 = 0, r1 = 0, r2 = 0, r3 = 0;
            for (int i = slice; i < TOPK; i += 8) {
                unsigned lr = s_lyry[i];
                int ly = (int)(lr & 0xFFFFu), ry = (int)(lr >> 16);
                if (row >= ly && row < ry) {
                    r0 |= s_m[0][i]; r1 |= s_m[1][i];
                    r2 |= s_m[2][i]; r3 |= s_m[3][i];
                }
            }
            if (r0) atomicOr(&s_bitmap[row][0], r0);
            if (r1) atomicOr(&s_bitmap[row][1], r1);
            if (r2) atomicOr(&s_bitmap[row][2], r2);
            if (r3) atomicOr(&s_bitmap[row][3], r3);
        }
    }
    __syncthreads();

    // ---- write output: masked (-1e20) unless covered && !padding ----
    const int vh = vfs[b * 2 + 0];
    const int vw = vfs[b * 2 + 1];
    float* obase = out + (size_t)b * FH * FW;
    for (int idx = tid; idx < FH * FW; idx += 1024) {
        int h = idx / FW;
        int w = idx - h * FW;
        bool cov = (s_bitmap[h][w >> 5] >> (w & 31)) & 1u;
        bool pad = (h >= vh) || (w >= vw);
        obase[idx] = (cov && !pad) ? 0.0f : -1e20f;
    }
}

// ---------------------------------------------------------------------------
extern "C" void kernel_launch(void* const* d_in, const int* in_sizes, int n_in,
                              void* d_out, int out_size) {
    const float* coord = (const float*)d_in[0];  // (BS, NQ, 4) f32
    const float* cls   = (const float*)d_in[1];  // (BS, NQ, NC) f32
    const int*   vfs   = (const int*)d_in[2];    // (BS, 2) i32
    float* out = (float*)d_out;                  // (BS, FH*FW) f32

    int nwarps = (BS * NQ) / 4;                  // one warp per 4 rows
    int threads = 256;
    int blocks = (nwarps * 32 + threads - 1) / threads;  // 6000
    scores_kernel<<<blocks, threads>>>(cls);
    mask_kernel<<<BS, 1024>>>(coord, vfs, out);
}

// round 5
// speedup vs baseline: 1.4555x; 1.1923x over previous
#include <cuda_runtime.h>
#include <cstdint>

#define BS   64
#define NQ   3000
#define NC   256
#define FH   100
#define FW   100
#define TOPK 1500

// Scratch for per-(b,q) scores (no cudaMalloc allowed).
__device__ float g_scores[BS * NQ];

// ---------------------------------------------------------------------------
// Kernel 1: scores[b,q] = max over NC=256 classes. One warp per 4 rows.
// 8 independent LDG.128 per thread (MLP_p1=8) to hide DRAM latency.
// ---------------------------------------------------------------------------
__global__ __launch_bounds__(256) void scores_kernel(const float* __restrict__ cls) {
    int warp = (blockIdx.x * blockDim.x + threadIdx.x) >> 5;
    int lane = threadIdx.x & 31;
    int row0 = warp * 4;
    if (row0 >= BS * NQ) return;

    const float4* r0 = reinterpret_cast<const float4*>(cls + (size_t)(row0 + 0) * NC);
    const float4* r1 = reinterpret_cast<const float4*>(cls + (size_t)(row0 + 1) * NC);
    const float4* r2 = reinterpret_cast<const float4*>(cls + (size_t)(row0 + 2) * NC);
    const float4* r3 = reinterpret_cast<const float4*>(cls + (size_t)(row0 + 3) * NC);

    float4 a0 = __ldcs(&r0[lane]);
    float4 b0 = __ldcs(&r0[lane + 32]);
    float4 a1 = __ldcs(&r1[lane]);
    float4 b1 = __ldcs(&r1[lane + 32]);
    float4 a2 = __ldcs(&r2[lane]);
    float4 b2 = __ldcs(&r2[lane + 32]);
    float4 a3 = __ldcs(&r3[lane]);
    float4 b3 = __ldcs(&r3[lane + 32]);

    float m0 = fmaxf(fmaxf(fmaxf(a0.x, a0.y), fmaxf(a0.z, a0.w)),
                     fmaxf(fmaxf(b0.x, b0.y), fmaxf(b0.z, b0.w)));
    float m1 = fmaxf(fmaxf(fmaxf(a1.x, a1.y), fmaxf(a1.z, a1.w)),
                     fmaxf(fmaxf(b1.x, b1.y), fmaxf(b1.z, b1.w)));
    float m2 = fmaxf(fmaxf(fmaxf(a2.x, a2.y), fmaxf(a2.z, a2.w)),
                     fmaxf(fmaxf(b2.x, b2.y), fmaxf(b2.z, b2.w)));
    float m3 = fmaxf(fmaxf(fmaxf(a3.x, a3.y), fmaxf(a3.z, a3.w)),
                     fmaxf(fmaxf(b3.x, b3.y), fmaxf(b3.z, b3.w)));
#pragma unroll
    for (int o = 16; o; o >>= 1) {
        m0 = fmaxf(m0, __shfl_xor_sync(0xFFFFFFFFu, m0, o));
        m1 = fmaxf(m1, __shfl_xor_sync(0xFFFFFFFFu, m1, o));
        m2 = fmaxf(m2, __shfl_xor_sync(0xFFFFFFFFu, m2, o));
        m3 = fmaxf(m3, __shfl_xor_sync(0xFFFFFFFFu, m3, o));
    }
    if (lane == 0)
        *reinterpret_cast<float4*>(&g_scores[row0]) = make_float4(m0, m1, m2, m3);
}

// Monotone float -> uint key (total order matches float compare for finite vals)
__device__ __forceinline__ unsigned f2key(float f) {
    unsigned u = __float_as_uint(f);
    return u ^ ((u >> 31) ? 0xFFFFFFFFu : 0x80000000u);
}

// ---------------------------------------------------------------------------
// Kernel 2: per-batch radix top-k threshold + rectangle-union mask paint.
// One block per batch, 1024 threads.
// ---------------------------------------------------------------------------
__global__ __launch_bounds__(1024) void mask_kernel(const float* __restrict__ coord,
                                                    const int*   __restrict__ vfs,
                                                    float*       __restrict__ out) {
    const int b    = blockIdx.x;
    const int tid  = threadIdx.x;
    const int lane = tid & 31;
    const int wid  = tid >> 5;

    __shared__ unsigned s_hist[256];      // radix histogram
    __shared__ unsigned s_sel[2];         // {selected byte, remaining need}
    __shared__ unsigned s_woff[32];       // scan warp offsets
    __shared__ unsigned s_lyry[TOPK];     // packed (ly | ry<<16)
    __shared__ uint4    s_m4[TOPK];       // column bitmasks (128 bits as uint4)

    // ---- load keys: 3 contiguous queries per thread (index order = scan order)
    unsigned k[3];
#pragma unroll
    for (int j = 0; j < 3; j++) {
        int q = tid * 3 + j;
        k[j] = (q < NQ) ? f2key(g_scores[b * NQ + q]) : 0u;
    }

    // ---- 8-bit radix select: find T = max{x : count_ge(x) >= TOPK} ----
    unsigned prefix = 0;
    unsigned need = TOPK;
#pragma unroll
    for (int pass = 0; pass < 4; pass++) {
        const int shift = 24 - 8 * pass;
        if (tid < 256) s_hist[tid] = 0u;
        __syncthreads();
#pragma unroll
        for (int j = 0; j < 3; j++) {
            unsigned kk = k[j];
            bool active = (pass == 0) || ((kk >> (shift + 8)) == prefix);
            if (active) atomicAdd(&s_hist[(kk >> shift) & 255u], 1u);
        }
        __syncthreads();
        if (tid < 32) {
            unsigned loc[8]; unsigned s = 0;
#pragma unroll
            for (int i = 0; i < 8; i++) { loc[i] = s_hist[lane * 8 + i]; s += loc[i]; }
            // v = sum over lanes >= lane (i.e. bins above mine + mine)
            unsigned v = s;
#pragma unroll
            for (int o = 1; o < 32; o <<= 1) {
                unsigned u = __shfl_down_sync(0xFFFFFFFFu, v, o);
                if (lane + o < 32) v += u;
            }
            unsigned excl = v - s;   // count in strictly higher 8-bin groups
            if (excl < need && excl + s >= need) {
                unsigned cum = excl;
#pragma unroll
                for (int i = 7; i >= 0; i--) {
                    unsigned c2 = cum + loc[i];
                    if (cum < need && c2 >= need) {
                        s_sel[0] = (unsigned)(lane * 8 + i);
                        s_sel[1] = need - cum;    // ties still required
                    }
                    cum = c2;
                }
            }
        }
        __syncthreads();
        prefix = (prefix << 8) | s_sel[0];
        need   = s_sel[1];
        __syncthreads();
    }
    const unsigned T = prefix;
    const unsigned need_eq = need;

    // ---- tie scan: rank among k==T in index order ----
    unsigned e = 0;
#pragma unroll
    for (int j = 0; j < 3; j++) e += (k[j] == T);
    unsigned my_off;
    {
        unsigned inc = e;
#pragma unroll
        for (int o = 1; o < 32; o <<= 1) {
            unsigned u = __shfl_up_sync(0xFFFFFFFFu, inc, o);
            if (lane >= o) inc += u;
        }
        if (lane == 31) s_woff[wid] = inc;
        __syncthreads();
        if (tid < 32) {
            unsigned v = s_woff[lane], i2 = v;
#pragma unroll
            for (int o = 1; o < 32; o <<= 1) {
                unsigned u = __shfl_up_sync(0xFFFFFFFFu, i2, o);
                if (lane >= o) i2 += u;
            }
            s_woff[lane] = i2 - v;
        }
        __syncthreads();
        my_off = s_woff[wid] + (inc - e);
    }

    // ---- selection flags + slot scan (no atomics) ----
    bool selj[3];
    unsigned selc = 0;
    {
        unsigned cum = 0;
#pragma unroll
        for (int j = 0; j < 3; j++) {
            int q = tid * 3 + j;
            bool s = false;
            if (q < NQ) {
                if (k[j] > T) s = true;
                else if (k[j] == T) { s = (my_off + cum < need_eq); cum++; }
            }
            selj[j] = s;
            selc += s;
        }
    }
    unsigned slot;
    {
        unsigned inc = selc;
#pragma unroll
        for (int o = 1; o < 32; o <<= 1) {
            unsigned u = __shfl_up_sync(0xFFFFFFFFu, inc, o);
            if (lane >= o) inc += u;
        }
        __syncthreads();                 // protect s_woff reuse
        if (lane == 31) s_woff[wid] = inc;
        __syncthreads();
        if (tid < 32) {
            unsigned v = s_woff[lane], i2 = v;
#pragma unroll
            for (int o = 1; o < 32; o <<= 1) {
                unsigned u = __shfl_up_sync(0xFFFFFFFFu, i2, o);
                if (lane >= o) i2 += u;
            }
            s_woff[lane] = i2 - v;
        }
        __syncthreads();
        slot = s_woff[wid] + (inc - selc);
    }

    // ---- build rects for selected queries ----
    const float fvh = (float)vfs[b * 2 + 0];
    const float fvw = (float)vfs[b * 2 + 1];
#pragma unroll
    for (int j = 0; j < 3; j++) {
        if (selj[j]) {
            int q = tid * 3 + j;
            float4 c4 = *reinterpret_cast<const float4*>(coord + ((size_t)b * NQ + q) * 4);
            // Non-contracted IEEE ops to match XLA bit-for-bit at floor boundaries
            float hw = __fmul_rn(0.5f, c4.z);
            float hh = __fmul_rn(0.5f, c4.w);
            float x0 = __fsub_rn(c4.x, hw);
            float y0 = __fsub_rn(c4.y, hh);
            float x1 = __fadd_rn(c4.x, hw);
            float y1 = __fadd_rn(c4.y, hh);
            int lx = (int)floorf(__fmul_rn(x0, fvh));
            int ly = (int)floorf(__fmul_rn(y0, fvw));
            int rx = (int)floorf(__fmul_rn(x1, fvh));
            int ry = (int)floorf(__fmul_rn(y1, fvw));
            int lc  = max(lx, 0), rc  = min(rx, FW);
            int lyc = max(ly, 0), ryc = min(ry, FH);
            if (ryc < lyc) ryc = lyc;    // empty row range
            s_lyry[slot] = (unsigned)lyc | ((unsigned)ryc << 16);
            unsigned mw[4];
#pragma unroll
            for (int w = 0; w < 4; w++) {
                int l = min(max(lc - 32 * w, 0), 32);
                int h = min(max(rc - 32 * w, 0), 32);
                unsigned m = 0;
                if (h > l) {
                    unsigned mh = (h == 32) ? 0xFFFFFFFFu : ((1u << h) - 1u);
                    m = mh & ~((1u << l) - 1u);   // l < 32 guaranteed here
                }
                mw[w] = m;
            }
            s_m4[slot] = make_uint4(mw[0], mw[1], mw[2], mw[3]);
            slot++;
        }
    }
    __syncthreads();

    // ---- paint: warp w owns rows {w, w+32, w+64, w+96(if w<4)}; exclusive
    // ownership -> no atomics, no bitmap. Lane l walks rects l, l+32, ...
    // (conflict-free LDS.128 + LDS.32), accumulates col-masks in registers.
    unsigned acc[4][4] = {{0u,0u,0u,0u},{0u,0u,0u,0u},{0u,0u,0u,0u},{0u,0u,0u,0u}};
    const bool has4 = (wid < 4);
    for (int i = lane; i < TOPK; i += 32) {
        uint4 m = s_m4[i];
        unsigned lr = s_lyry[i];
        unsigned ly = lr & 0xFFFFu, ry = lr >> 16;
#pragma unroll
        for (int s = 0; s < 3; s++) {
            unsigned row = (unsigned)(wid + 32 * s);
            if (row >= ly && row < ry) {
                acc[s][0] |= m.x; acc[s][1] |= m.y;
                acc[s][2] |= m.z; acc[s][3] |= m.w;
            }
        }
        if (has4) {
            unsigned row = (unsigned)(wid + 96);
            if (row >= ly && row < ry) {
                acc[3][0] |= m.x; acc[3][1] |= m.y;
                acc[3][2] |= m.z; acc[3][3] |= m.w;
            }
        }
    }

    // warp OR-reduce each accumulated word (result in all lanes)
#pragma unroll
    for (int s = 0; s < 4; s++)
#pragma unroll
        for (int c = 0; c < 4; c++)
#pragma unroll
            for (int o = 16; o; o >>= 1)
                acc[s][c] |= __shfl_xor_sync(0xFFFFFFFFu, acc[s][c], o);

    // ---- write output directly (fused bitmap + padding), fully coalesced ----
    const int vh = vfs[b * 2 + 0];
    const int vw = vfs[b * 2 + 1];
    float* obase = out + (size_t)b * FH * FW;
#pragma unroll
    for (int s = 0; s < 4; s++) {
        int row = wid + 32 * s;
        if (s < 3 || has4) {
#pragma unroll
            for (int c = 0; c < 4; c++) {
                int col = lane + 32 * c;
                if (col < FW) {
                    bool cov = (acc[s][c] >> lane) & 1u;
                    bool ok  = cov && (row < vh) && (col < vw);
                    obase[row * FW + col] = ok ? 0.0f : -1e20f;
                }
            }
        }
    }
}

// ---------------------------------------------------------------------------
extern "C" void kernel_launch(void* const* d_in, const int* in_sizes, int n_in,
                              void* d_out, int out_size) {
    const float* coord = (const float*)d_in[0];  // (BS, NQ, 4) f32
    const float* cls   = (const float*)d_in[1];  // (BS, NQ, NC) f32
    const int*   vfs   = (const int*)d_in[2];    // (BS, 2) i32
    float* out = (float*)d_out;                  // (BS, FH*FW) f32

    int nwarps = (BS * NQ) / 4;                  // one warp per 4 rows
    int threads = 256;
    int blocks = (nwarps * 32 + threads - 1) / threads;  // 6000
    scores_kernel<<<blocks, threads>>>(cls);
    mask_kernel<<<BS, 1024>>>(coord, vfs, out);
}